// round 8
// baseline (speedup 1.0000x reference)
#include <cuda_runtime.h>
#include <math.h>

#define NN 50000
#define NE 1600000

// ---------------- device scratch; NEVER passed as kernel args ----------------
__device__ int    g_is64;
__device__ float  g_deg[NN];
__device__ float  g_dinv[NN];
__device__ int    g_count[NN];
__device__ int    g_rowptr[NN + 1];
__device__ int    g_fill[NN];
__device__ int    g_src[NE];
__device__ int    g_dst[NE];
__device__ int    g_csr_src[NE];
__device__ float  g_csr_norm[NE];
__device__ __align__(16) float g_H1[NN * 64];   // features @ W1
__device__ __align__(16) float g_h1[NN * 64];   // relu(agg1 + b1)
__device__ __align__(16) float g_H2[NN * 32];   // h1 @ W2
__device__ __align__(16) float g_z [NN * 32];   // tanh(agg2 + b2)
__device__ __align__(16) float g_Hd[NN * 2];    // (tile(z,4)+feat) @ Wd
__device__ double g_acc;

// ---------------- init ----------------
__global__ void k_init() {
    int i = blockIdx.x * blockDim.x + threadIdx.x;
    if (i < NN) { g_deg[i] = 1.0f; g_count[i] = 0; }   // deg starts at self-loop weight 1
    if (i == 0) g_acc = 0.0;
}

// int64 vs int32 detection (int64 little-endian: odd 32-bit words all zero)
__global__ void k_detect(const int* __restrict__ ei) {
    if (threadIdx.x == 0 && blockIdx.x == 0) {
        int all0 = 1;
        for (int i = 0; i < 256; i++)
            if (ei[2 * i + 1] != 0) { all0 = 0; break; }
        g_is64 = all0;
    }
}

// decode edges; weighted degree + per-dst edge count
__global__ void k_edges1(const void* __restrict__ ei, const float* __restrict__ w) {
    int e = blockIdx.x * blockDim.x + threadIdx.x;
    if (e >= NE) return;
    int s, d;
    if (g_is64) {
        const int2* p = (const int2*)ei;
        s = p[e].x; d = p[e + NE].x;
    } else {
        const int* p = (const int*)ei;
        s = p[e]; d = p[e + NE];
    }
    g_src[e] = s; g_dst[e] = d;
    atomicAdd(&g_deg[d], w[e]);
    atomicAdd(&g_count[d], 1);
}

__global__ void k_dinv() {
    int i = blockIdx.x * blockDim.x + threadIdx.x;
    if (i < NN) g_dinv[i] = (float)(1.0 / sqrt((double)g_deg[i]));  // deg >= 1
}

// single-block exclusive scan of g_count -> g_rowptr, g_fill
__global__ void k_scan() {
    __shared__ int s[1024];
    const int CH = (NN + 1023) / 1024;  // 49
    int t = threadIdx.x;
    int begin = t * CH;
    int end = begin + CH; if (end > NN) end = NN;
    if (begin > NN) begin = NN;
    int sum = 0;
    for (int i = begin; i < end; i++) sum += g_count[i];
    s[t] = sum;
    __syncthreads();
    for (int off = 1; off < 1024; off <<= 1) {
        int v = (t >= off) ? s[t - off] : 0;
        __syncthreads();
        s[t] += v;
        __syncthreads();
    }
    int run = (t == 0) ? 0 : s[t - 1];
    for (int i = begin; i < end; i++) {
        g_rowptr[i] = run;
        g_fill[i]   = run;
        run += g_count[i];
    }
    if (t == 1023) g_rowptr[NN] = s[1023];
}

// scatter edges into dst-CSR with precomputed norm
__global__ void k_build_csr(const float* __restrict__ w) {
    int e = blockIdx.x * blockDim.x + threadIdx.x;
    if (e >= NE) return;
    int s = g_src[e], d = g_dst[e];
    float norm = g_dinv[s] * w[e] * g_dinv[d];
    int pos = atomicAdd(&g_fill[d], 1);
    g_csr_src[pos]  = s;
    g_csr_norm[pos] = norm;
}

// ---------------- GEMM1: g_H1 = features @ W1  (128 -> 64) ----------------
__global__ void k_gemm1(const float* __restrict__ X, const float* __restrict__ W) {
    __shared__ float Ws[128 * 64];
    for (int i = threadIdx.x; i < 128 * 64; i += blockDim.x) Ws[i] = W[i];
    __syncthreads();
    int row = blockIdx.x * blockDim.x + threadIdx.x;
    if (row >= NN) return;
    float acc[64];
#pragma unroll
    for (int j = 0; j < 64; j++) acc[j] = 0.0f;
    const float* x = X + (long)row * 128;
    for (int k = 0; k < 128; k += 4) {
        float4 f = *(const float4*)(x + k);
#pragma unroll
        for (int j = 0; j < 64; j++) acc[j] = fmaf(f.x, Ws[(k + 0) * 64 + j], acc[j]);
#pragma unroll
        for (int j = 0; j < 64; j++) acc[j] = fmaf(f.y, Ws[(k + 1) * 64 + j], acc[j]);
#pragma unroll
        for (int j = 0; j < 64; j++) acc[j] = fmaf(f.z, Ws[(k + 2) * 64 + j], acc[j]);
#pragma unroll
        for (int j = 0; j < 64; j++) acc[j] = fmaf(f.w, Ws[(k + 3) * 64 + j], acc[j]);
    }
    float* y = g_H1 + (long)row * 64;
#pragma unroll
    for (int j = 0; j < 64; j++) y[j] = acc[j];
}

// ---------------- agg1: g_h1 = relu( dinv^2*H1[i] + sum_in H1[src]*norm + b1 ) ----------------
__global__ void k_agg1(const float* __restrict__ b) {
    int lane = threadIdx.x & 63;
    int node = blockIdx.x * 4 + (threadIdx.x >> 6);
    if (node >= NN) return;
    float di = g_dinv[node];
    float acc = di * di * g_H1[(long)node * 64 + lane];
    int p0 = g_rowptr[node], p1 = g_rowptr[node + 1];
    for (int p = p0; p < p1; p++) {
        int s   = g_csr_src[p];
        float n = g_csr_norm[p];
        acc = fmaf(g_H1[(long)s * 64 + lane], n, acc);
    }
    acc += b[lane];
    g_h1[(long)node * 64 + lane] = fmaxf(acc, 0.0f);
}

// ---------------- GEMM2: g_H2 = g_h1 @ W2  (64 -> 32) ----------------
__global__ void k_gemm2(const float* __restrict__ W) {
    __shared__ float Ws[64 * 32];
    for (int i = threadIdx.x; i < 64 * 32; i += blockDim.x) Ws[i] = W[i];
    __syncthreads();
    int row = blockIdx.x * blockDim.x + threadIdx.x;
    if (row >= NN) return;
    float acc[32];
#pragma unroll
    for (int j = 0; j < 32; j++) acc[j] = 0.0f;
    const float* x = g_h1 + (long)row * 64;
    for (int k = 0; k < 64; k += 4) {
        float4 f = *(const float4*)(x + k);
#pragma unroll
        for (int j = 0; j < 32; j++) acc[j] = fmaf(f.x, Ws[(k + 0) * 32 + j], acc[j]);
#pragma unroll
        for (int j = 0; j < 32; j++) acc[j] = fmaf(f.y, Ws[(k + 1) * 32 + j], acc[j]);
#pragma unroll
        for (int j = 0; j < 32; j++) acc[j] = fmaf(f.z, Ws[(k + 2) * 32 + j], acc[j]);
#pragma unroll
        for (int j = 0; j < 32; j++) acc[j] = fmaf(f.w, Ws[(k + 3) * 32 + j], acc[j]);
    }
    float* y = g_H2 + (long)row * 32;
#pragma unroll
    for (int j = 0; j < 32; j++) y[j] = acc[j];
}

// ---------------- agg2: g_z = tanh( dinv^2*H2[i] + sum_in H2[src]*norm + b2 ) ----------------
__global__ void k_agg2(const float* __restrict__ b) {
    int lane = threadIdx.x & 31;
    int node = blockIdx.x * 8 + (threadIdx.x >> 5);
    if (node >= NN) return;
    float di = g_dinv[node];
    float acc = di * di * g_H2[(long)node * 32 + lane];
    int p0 = g_rowptr[node], p1 = g_rowptr[node + 1];
    for (int p = p0; p < p1; p++) {
        int s   = g_csr_src[p];
        float n = g_csr_norm[p];
        acc = fmaf(g_H2[(long)s * 32 + lane], n, acc);
    }
    acc += b[lane];
    g_z[(long)node * 32 + lane] = (float)tanh((double)acc);
}

// ---------------- Hd = (tile(z,4) + feat) @ Wd, z-fold (no x materialization) ----------------
__global__ void k_gemmd(const float* __restrict__ feat, const float* __restrict__ Wd) {
    __shared__ float Wds[128 * 2];
    __shared__ float Wzs[32 * 2];
    for (int i = threadIdx.x; i < 256; i += blockDim.x) Wds[i] = Wd[i];
    __syncthreads();
    if (threadIdx.x < 64) {
        int c = threadIdx.x >> 1, k = threadIdx.x & 1;
        Wzs[c * 2 + k] = Wds[c * 2 + k] + Wds[(c + 32) * 2 + k] +
                         Wds[(c + 64) * 2 + k] + Wds[(c + 96) * 2 + k];
    }
    __syncthreads();
    int node = blockIdx.x * blockDim.x + threadIdx.x;
    if (node >= NN) return;
    float a0 = 0.0f, a1 = 0.0f;
    const float* f = feat + (long)node * 128;
    for (int c = 0; c < 128; c += 4) {
        float4 v = *(const float4*)(f + c);
        a0 = fmaf(v.x, Wds[(c + 0) * 2], a0); a0 = fmaf(v.y, Wds[(c + 1) * 2], a0);
        a0 = fmaf(v.z, Wds[(c + 2) * 2], a0); a0 = fmaf(v.w, Wds[(c + 3) * 2], a0);
        a1 = fmaf(v.x, Wds[(c + 0) * 2 + 1], a1); a1 = fmaf(v.y, Wds[(c + 1) * 2 + 1], a1);
        a1 = fmaf(v.z, Wds[(c + 2) * 2 + 1], a1); a1 = fmaf(v.w, Wds[(c + 3) * 2 + 1], a1);
    }
    const float* zz = g_z + (long)node * 32;
    for (int c = 0; c < 32; c += 4) {
        float4 v = *(const float4*)(zz + c);
        a0 = fmaf(v.x, Wzs[(c + 0) * 2], a0); a0 = fmaf(v.y, Wzs[(c + 1) * 2], a0);
        a0 = fmaf(v.z, Wzs[(c + 2) * 2], a0); a0 = fmaf(v.w, Wzs[(c + 3) * 2], a0);
        a1 = fmaf(v.x, Wzs[(c + 0) * 2 + 1], a1); a1 = fmaf(v.y, Wzs[(c + 1) * 2 + 1], a1);
        a1 = fmaf(v.z, Wzs[(c + 2) * 2 + 1], a1); a1 = fmaf(v.w, Wzs[(c + 3) * 2 + 1], a1);
    }
    g_Hd[2 * node]     = a0;
    g_Hd[2 * node + 1] = a1;
}

// ---------------- agg3 + relu + dot with w_fc fused (warp per node, double accum) ----------------
__global__ void k_aggd_dot(const float* __restrict__ bd, const float* __restrict__ w_fc) {
    int warp = threadIdx.x >> 5, lane = threadIdx.x & 31;
    int node = blockIdx.x * 8 + warp;
    float a0 = 0.0f, a1 = 0.0f;
    int p0 = g_rowptr[node], p1 = g_rowptr[node + 1];
    for (int p = p0 + lane; p < p1; p += 32) {
        int s   = g_csr_src[p];
        float n = g_csr_norm[p];
        float2 h = *(const float2*)(g_Hd + 2 * s);
        a0 = fmaf(h.x, n, a0);
        a1 = fmaf(h.y, n, a1);
    }
#pragma unroll
    for (int off = 16; off > 0; off >>= 1) {
        a0 += __shfl_down_sync(0xffffffffu, a0, off);
        a1 += __shfl_down_sync(0xffffffffu, a1, off);
    }
    double val = 0.0;
    if (lane == 0) {
        float di = g_dinv[node];
        a0 += di * di * g_Hd[2 * node] + bd[0];
        a1 += di * di * g_Hd[2 * node + 1] + bd[1];
        val = (double)fmaxf(a0, 0.0f) * (double)w_fc[2 * node]
            + (double)fmaxf(a1, 0.0f) * (double)w_fc[2 * node + 1];
    }
    __shared__ double sv[8];
    if (lane == 0) sv[warp] = val;
    __syncthreads();
    if (threadIdx.x == 0) {
        double t = sv[0] + sv[1] + sv[2] + sv[3] + sv[4] + sv[5] + sv[6] + sv[7];
        atomicAdd(&g_acc, t);
    }
}

__global__ void k_final(const float* __restrict__ b_fc, float* __restrict__ out) {
    if (threadIdx.x == 0 && blockIdx.x == 0) {
        double logit = g_acc + (double)b_fc[0];
        out[0] = (float)(1.0 / (1.0 + exp(-logit)));
    }
}

// ---------------- launch: ONLY harness pointers cross host->device ----------------
extern "C" void kernel_launch(void* const* d_in, const int* in_sizes, int n_in,
                              void* d_out, int out_size) {
    const float* features = (const float*)d_in[0];
    const void*  edge_idx = d_in[1];
    const float* edge_w   = (const float*)d_in[2];
    const float* W1   = (const float*)d_in[3];
    const float* b1   = (const float*)d_in[4];
    const float* W2   = (const float*)d_in[5];
    const float* b2   = (const float*)d_in[6];
    const float* Wd   = (const float*)d_in[7];
    const float* bd   = (const float*)d_in[8];
    const float* w_fc = (const float*)d_in[9];
    const float* b_fc = (const float*)d_in[10];
    float* out = (float*)d_out;

    const int NB_N = (NN + 255) / 256;
    const int NB_E = (NE + 255) / 256;

    k_init<<<NB_N, 256>>>();
    k_detect<<<1, 32>>>((const int*)edge_idx);
    k_edges1<<<NB_E, 256>>>(edge_idx, edge_w);
    k_dinv<<<NB_N, 256>>>();
    k_scan<<<1, 1024>>>();
    k_build_csr<<<NB_E, 256>>>(edge_w);

    k_gemm1<<<NB_N, 256>>>(features, W1);
    k_agg1<<<NN / 4, 256>>>(b1);

    k_gemm2<<<NB_N, 256>>>(W2);
    k_agg2<<<NN / 8, 256>>>(b2);

    k_gemmd<<<NB_N, 256>>>(features, Wd);
    k_aggd_dot<<<NN / 8, 256>>>(bd, w_fc);

    k_final<<<1, 32>>>(b_fc, out);
    (void)in_sizes; (void)n_in; (void)out_size;
}